// round 6
// baseline (speedup 1.0000x reference)
#include <cuda_runtime.h>
#include <math_constants.h>

#define BB 4
#define NN 512
#define HH 8
#define FF 16
#define DH 128
#define TJ 16
#define PN 8    // nodes per proj block
#define AW 16   // warps per attn block
#define LOG2E 1.44269504f

typedef unsigned long long u64;
#define ABSMASK2 0x7FFFFFFF7FFFFFFFull

__device__ __forceinline__ u64 addx2(u64 a, u64 b){ u64 d; asm("add.rn.f32x2 %0,%1,%2;" : "=l"(d) : "l"(a), "l"(b)); return d; }
__device__ __forceinline__ u64 mulx2(u64 a, u64 b){ u64 d; asm("mul.rn.f32x2 %0,%1,%2;" : "=l"(d) : "l"(a), "l"(b)); return d; }
__device__ __forceinline__ u64 fmax2(u64 a, u64 b, u64 c){ u64 d; asm("fma.rn.f32x2 %0,%1,%2,%3;" : "=l"(d) : "l"(a), "l"(b), "l"(c)); return d; }
__device__ __forceinline__ u64 pk2(float x, float y){ u64 r; asm("mov.b64 %0, {%1,%2};" : "=l"(r) : "r"(__float_as_uint(x)), "r"(__float_as_uint(y))); return r; }
__device__ __forceinline__ float2 unpk2(u64 v){ unsigned lo, hi; asm("mov.b64 {%0,%1}, %2;" : "=r"(lo), "=r"(hi) : "l"(v)); return make_float2(__uint_as_float(lo), __uint_as_float(hi)); }
__device__ __forceinline__ float ex2(float x){ float r; asm("ex2.approx.f32 %0,%1;" : "=f"(r) : "f"(x)); return r; }

// ---- scratch ----
__device__ float    d_h[2][BB*NN*DH];
__device__ float    d_gl[BB*NN*DH];
__device__ float    d_gr[BB*NN*DH];
__device__ float    d_dl[BB*NN*HH];          // log2e * 0.6 * (a . g_l[n,h,:])
__device__ unsigned d_adjbits[BB*NN*(NN/32)];

// ---- tiny: zero the output (keeps ncu -s 5 on attn) ----
__global__ void zero_kernel(float* __restrict__ out)
{
    int i = blockIdx.x * 256 + threadIdx.x;
    if (i < BB*NN) out[i] = 0.f;
}

// ---- fused: h0 = X @ W_in, adj bit-packing ----
__global__ void prep_kernel(const float* __restrict__ x, const float* __restrict__ Win,
                            const int* __restrict__ adj)
{
    if (blockIdx.x < 1024) {
        int idx = blockIdx.x * 256 + threadIdx.x;
        int n = idx >> 7, d = idx & 127;
        d_h[0][idx] = fmaf(x[n*2], Win[d], x[n*2+1] * Win[DH + d]);
    } else {
        int gw   = ((blockIdx.x - 1024) * 256 + threadIdx.x) >> 5;
        int lane = threadIdx.x & 31;
        const int* row = adj + gw * NN;
        #pragma unroll
        for (int w = 0; w < NN/32; w++) {
            unsigned bits = __ballot_sync(0xffffffffu, row[w*32 + lane] != 0);
            if (lane == 0) d_adjbits[gw*(NN/32) + w] = bits;
        }
    }
}

// ---- projections: streaming double-buffered W, f32x2 node-pair math ----
__global__ void __launch_bounds__(256, 3) proj_kernel(const float* __restrict__ Wl,
                                                      const float* __restrict__ Wr,
                                                      const float* __restrict__ a, int src)
{
    __shared__ __align__(16) float sw[2][16][256];
    __shared__ __align__(16) u64   sph[DH][PN/2];

    int n0 = blockIdx.x * PN;
    int t  = threadIdx.x;

    {
        const float* h = d_h[src];
        #pragma unroll
        for (int r = 0; r < 2; r++) {
            int idx = r*256 + t;
            int k = idx >> 2, p = idx & 3;
            sph[k][p] = pk2(h[(n0 + 2*p)*DH + k], h[(n0 + 2*p + 1)*DH + k]);
        }
    }

    float4 rw[4];
    auto ldg_chunk = [&](int ck) {
        #pragma unroll
        for (int q = 0; q < 4; q++) {
            int idx = q*256 + t;
            int kk = idx >> 6, c4 = idx & 63;
            int k = ck*16 + kk;
            const float* s = (c4 < 32) ? (Wl + k*DH + c4*4) : (Wr + k*DH + (c4-32)*4);
            rw[q] = *(const float4*)s;
        }
    };
    auto sts_chunk = [&](int buf) {
        #pragma unroll
        for (int q = 0; q < 4; q++) {
            int idx = q*256 + t;
            int kk = idx >> 6, c4 = idx & 63;
            *(float4*)&sw[buf][kk][c4*4] = rw[q];
        }
    };

    ldg_chunk(0); sts_chunk(0);
    ldg_chunk(1);
    __syncthreads();

    int c = t;
    u64 acc2[PN/2];
    #pragma unroll
    for (int p = 0; p < PN/2; p++) acc2[p] = 0ull;

    #pragma unroll
    for (int ck = 0; ck < 8; ck++) {
        int buf = ck & 1;
        #pragma unroll
        for (int kk = 0; kk < 16; kk++) {
            float w = sw[buf][kk][c];
            u64 w2 = pk2(w, w);
            const ulonglong2* hp = (const ulonglong2*)&sph[ck*16 + kk][0];
            ulonglong2 h01 = hp[0], h23 = hp[1];
            acc2[0] = fmax2(h01.x, w2, acc2[0]);
            acc2[1] = fmax2(h01.y, w2, acc2[1]);
            acc2[2] = fmax2(h23.x, w2, acc2[2]);
            acc2[3] = fmax2(h23.y, w2, acc2[3]);
        }
        if (ck < 7) {
            sts_chunk((ck + 1) & 1);
            if (ck < 6) ldg_chunk(ck + 2);
            __syncthreads();
        }
    }

    int sel = c >> 7, d = c & 127;
    float* g = sel ? d_gr : d_gl;
    #pragma unroll
    for (int p = 0; p < PN/2; p++) {
        float2 v = unpk2(acc2[p]);
        g[(n0 + 2*p)*DH + d]     = v.x;
        g[(n0 + 2*p + 1)*DH + d] = v.y;
    }
    if (sel == 0) {
        float av = 0.6f * LOG2E * a[d & 15];    // pre-scaled by log2e for ex2
        u64 av2 = pk2(av, av);
        u64 pr[PN/2];
        #pragma unroll
        for (int p = 0; p < PN/2; p++) pr[p] = mulx2(acc2[p], av2);
        #pragma unroll
        for (int off = 8; off; off >>= 1) {
            #pragma unroll
            for (int p = 0; p < PN/2; p++)
                pr[p] = addx2(pr[p], __shfl_down_sync(0xffffffffu, pr[p], off, 16));
        }
        if ((d & 15) == 0) {
            int hh = d >> 4;
            #pragma unroll
            for (int p = 0; p < PN/2; p++) {
                float2 v = unpk2(pr[p]);
                d_dl[(n0 + 2*p)*HH + hh]     = v.x;
                d_dl[(n0 + 2*p + 1)*HH + hh] = v.y;
            }
        }
    }
}

// ---- fused GATv2 attention: 16 warps/block, 32 j each, unioned smem ----
// e2_j = log2e*[0.6(a.gl_j) + sum_f 0.4 a_f |gr_i + gl_j|_f]; p = 2^e2 (no-max
// softmax: logits O(30), fp32-safe; per-i shift dropped by shift-invariance).
__global__ void __launch_bounds__(512, 2) attn_kernel(const float* __restrict__ a,
                                                      const float* __restrict__ Wout,
                                                      float* __restrict__ out,
                                                      int src, int last)
{
    // pool: during compute, warp wq's tiles live at [wq*288 .. wq*288+256):
    //   gl2 of j at wq*288 + j*16 + 0..7, gr2 at +8..15  (only j<16 used per tile)
    // after compute (guarded by __syncthreads), reused as merge staging:
    //   acc of (w, lane, q) at (w*32+lane)*9 + q   (stride 9 kills bank conflicts)
    __shared__ __align__(16) u64 s_pool[AW*288];           // 36KB
    __shared__ float s_dl[AW][TJ];
    __shared__ float s_l[AW][32];

    int blk   = blockIdx.x;
    int itile = blk & 15;
    int hh    = (blk >> 4) & 7;
    int b     = blk >> 7;
    int wq    = threadIdx.x >> 5;            // 0..15, owns j in [wq*32, wq*32+32)
    int lane  = threadIdx.x & 31;
    int i     = itile * 32 + lane;
    int ni    = b * NN + i;

    u64 ar2[FF/2];
    #pragma unroll
    for (int q = 0; q < FF/2; q++)
        ar2[q] = pk2(0.4f * LOG2E * a[2*q], 0.4f * LOG2E * a[2*q+1]);

    u64 gri2[FF/2];
    {
        const ulonglong2* gp = (const ulonglong2*)(d_gr + (ni*HH + hh)*FF);
        #pragma unroll
        for (int q = 0; q < 4; q++) {
            ulonglong2 v = gp[q];
            gri2[2*q] = v.x; gri2[2*q+1] = v.y;
        }
    }

    const float*    glbase = d_gl + (b*NN*HH + hh)*FF;
    const float*    grbase = d_gr + (b*NN*HH + hh)*FF;
    const unsigned* abr    = d_adjbits + ni*(NN/32);

    float l = 0.f;
    u64 acc2[FF/2];
    #pragma unroll
    for (int q = 0; q < FF/2; q++) acc2[q] = 0ull;

    u64* tile = &s_pool[wq * 288];

    #pragma unroll
    for (int t = 0; t < 2; t++) {                // 2 tiles of 16 j per warp
        int j0 = wq * 32 + t * TJ;
        __syncwarp();
        #pragma unroll
        for (int r = 0; r < 2; r++) {
            int idx = lane + r*32;               // 0..63 float4s per array
            int j = idx >> 2, v = idx & 3;
            *(float4*)&tile[j*16 + v*2]     = *((const float4*)(glbase + (j0+j)*(HH*FF)) + v);
            *(float4*)&tile[j*16 + 8 + v*2] = *((const float4*)(grbase + (j0+j)*(HH*FF)) + v);
        }
        if (lane < TJ) s_dl[wq][lane] = d_dl[(b*NN + j0 + lane)*HH + hh];
        __syncwarp();

        unsigned mbits = abr[j0 >> 5] >> ((j0 & 31));
        if (t) mbits >>= 0;                      // (j0&31)==t*16 within word handled below
        mbits = abr[j0 >> 5] >> (j0 & 31);
        #pragma unroll
        for (int j = 0; j < TJ; j++) {
            const ulonglong2* g2 = (const ulonglong2*)&tile[j*16];
            u64 s0 = 0ull, s1 = 0ull;
            #pragma unroll
            for (int q = 0; q < 4; q++) {
                ulonglong2 gv = g2[q];
                u64 t0 = addx2(gri2[2*q],   gv.x) & ABSMASK2;
                u64 t1 = addx2(gri2[2*q+1], gv.y) & ABSMASK2;
                s0 = fmax2(ar2[2*q],   t0, s0);
                s1 = fmax2(ar2[2*q+1], t1, s1);
            }
            float2 sv = unpk2(addx2(s0, s1));
            float ej = (sv.x + sv.y) + s_dl[wq][j];
            float pe = ex2(ej);
            float p  = ((mbits >> j) & 1u) ? pe : 0.f;
            l += p;
            u64 p2 = pk2(p, p);
            const ulonglong2* gr2 = (const ulonglong2*)&tile[j*16 + 8];
            #pragma unroll
            for (int q = 0; q < 4; q++) {
                ulonglong2 gv = gr2[q];
                acc2[2*q]   = fmax2(p2, gv.x, acc2[2*q]);
                acc2[2*q+1] = fmax2(p2, gv.y, acc2[2*q+1]);
            }
        }
    }

    __syncthreads();                             // all tiles consumed; pool reusable
    s_l[wq][lane] = l;
    #pragma unroll
    for (int q = 0; q < FF/2; q++)
        s_pool[(wq*32 + lane)*9 + q] = acc2[q];
    __syncthreads();

    // parallel merge: warp q (q<8) owns f32x2 component q for all 32 i
    if (wq < 8) {
        int q = wq;
        float L = 0.f;
        u64 o = 0ull;
        #pragma unroll
        for (int w = 0; w < AW; w++) {
            L += s_l[w][lane];
            o = addx2(o, s_pool[(w*32 + lane)*9 + q]);
        }
        float inv = 1.f / L;
        if (!last) {
            u64* ho = (u64*)(d_h[src ^ 1] + (ni*HH + hh)*FF);
            ho[q] = mulx2(o, pk2(inv, inv));
        } else {
            const float* wo = Wout + hh*FF;
            float2 ov = unpk2(o);
            float s = (ov.x * wo[2*q] + ov.y * wo[2*q+1]) * inv;
            atomicAdd(&out[ni], s);
        }
    }
}

extern "C" void kernel_launch(void* const* d_in, const int* in_sizes, int n_in,
                              void* d_out, int out_size)
{
    const float* nf   = (const float*)d_in[0];
    const int*   adj  = (const int*)  d_in[1];
    const float* Win  = (const float*)d_in[2];
    const float* Wl   = (const float*)d_in[3];
    const float* Wr   = (const float*)d_in[4];
    const float* aa   = (const float*)d_in[5];
    const float* Wout = (const float*)d_in[6];
    float* out = (float*)d_out;
    (void)in_sizes; (void)n_in; (void)out_size;

    zero_kernel<<<8, 256>>>(out);
    prep_kernel<<<1024 + 256, 256>>>(nf, Win, adj);
    for (int L = 0; L < 3; L++) {
        int src = L & 1;
        proj_kernel<<<(BB*NN)/PN, 256>>>(Wl + L*DH*DH, Wr + L*DH*DH, aa + L*FF, src);
        attn_kernel<<<BB*HH*(NN/32), 512>>>(aa + L*FF, Wout, out, src, L == 2);
    }
}

// round 7
// speedup vs baseline: 1.0693x; 1.0693x over previous
#include <cuda_runtime.h>
#include <math_constants.h>

#define BB 4
#define NN 512
#define HH 8
#define FF 16
#define DH 128
#define TJ 16
#define PN 8    // nodes per proj block
#define AW 16   // warps per attn block
#define LOG2E 1.44269504f

typedef unsigned long long u64;
#define ABSMASK2 0x7FFFFFFF7FFFFFFFull

__device__ __forceinline__ u64 addx2(u64 a, u64 b){ u64 d; asm("add.rn.f32x2 %0,%1,%2;" : "=l"(d) : "l"(a), "l"(b)); return d; }
__device__ __forceinline__ u64 mulx2(u64 a, u64 b){ u64 d; asm("mul.rn.f32x2 %0,%1,%2;" : "=l"(d) : "l"(a), "l"(b)); return d; }
__device__ __forceinline__ u64 fmax2(u64 a, u64 b, u64 c){ u64 d; asm("fma.rn.f32x2 %0,%1,%2,%3;" : "=l"(d) : "l"(a), "l"(b), "l"(c)); return d; }
__device__ __forceinline__ u64 pk2(float x, float y){ u64 r; asm("mov.b64 %0, {%1,%2};" : "=l"(r) : "r"(__float_as_uint(x)), "r"(__float_as_uint(y))); return r; }
__device__ __forceinline__ float2 unpk2(u64 v){ unsigned lo, hi; asm("mov.b64 {%0,%1}, %2;" : "=r"(lo), "=r"(hi) : "l"(v)); return make_float2(__uint_as_float(lo), __uint_as_float(hi)); }
__device__ __forceinline__ float ex2(float x){ float r; asm("ex2.approx.f32 %0,%1;" : "=f"(r) : "f"(x)); return r; }

// ---- scratch ----
__device__ float    d_h[2][BB*NN*DH];
__device__ float    d_gl[BB*NN*DH];
__device__ float    d_gr[BB*NN*DH];
__device__ float    d_dl[BB*NN*HH];          // log2e * 0.6 * (a . g_l[n,h,:])
__device__ unsigned d_adjbits[BB*NN*(NN/32)];

// ---- tiny: zero the output (keeps ncu -s 5 on attn) ----
__global__ void zero_kernel(float* __restrict__ out)
{
    int i = blockIdx.x * 256 + threadIdx.x;
    if (i < BB*NN) out[i] = 0.f;
}

// ---- fused: h0 = X @ W_in, adj bit-packing ----
__global__ void prep_kernel(const float* __restrict__ x, const float* __restrict__ Win,
                            const int* __restrict__ adj)
{
    if (blockIdx.x < 1024) {
        int idx = blockIdx.x * 256 + threadIdx.x;
        int n = idx >> 7, d = idx & 127;
        d_h[0][idx] = fmaf(x[n*2], Win[d], x[n*2+1] * Win[DH + d]);
    } else {
        int gw   = ((blockIdx.x - 1024) * 256 + threadIdx.x) >> 5;
        int lane = threadIdx.x & 31;
        const int* row = adj + gw * NN;
        #pragma unroll
        for (int w = 0; w < NN/32; w++) {
            unsigned bits = __ballot_sync(0xffffffffu, row[w*32 + lane] != 0);
            if (lane == 0) d_adjbits[gw*(NN/32) + w] = bits;
        }
    }
}

// ---- projections: streaming double-buffered W, f32x2 node-pair math ----
__global__ void __launch_bounds__(256, 3) proj_kernel(const float* __restrict__ Wl,
                                                      const float* __restrict__ Wr,
                                                      const float* __restrict__ a, int src)
{
    __shared__ __align__(16) float sw[2][16][256];
    __shared__ __align__(16) u64   sph[DH][PN/2];

    int n0 = blockIdx.x * PN;
    int t  = threadIdx.x;

    {
        const float* h = d_h[src];
        #pragma unroll
        for (int r = 0; r < 2; r++) {
            int idx = r*256 + t;
            int k = idx >> 2, p = idx & 3;
            sph[k][p] = pk2(h[(n0 + 2*p)*DH + k], h[(n0 + 2*p + 1)*DH + k]);
        }
    }

    float4 rw[4];
    auto ldg_chunk = [&](int ck) {
        #pragma unroll
        for (int q = 0; q < 4; q++) {
            int idx = q*256 + t;
            int kk = idx >> 6, c4 = idx & 63;
            int k = ck*16 + kk;
            const float* s = (c4 < 32) ? (Wl + k*DH + c4*4) : (Wr + k*DH + (c4-32)*4);
            rw[q] = *(const float4*)s;
        }
    };
    auto sts_chunk = [&](int buf) {
        #pragma unroll
        for (int q = 0; q < 4; q++) {
            int idx = q*256 + t;
            int kk = idx >> 6, c4 = idx & 63;
            *(float4*)&sw[buf][kk][c4*4] = rw[q];
        }
    };

    ldg_chunk(0); sts_chunk(0);
    ldg_chunk(1);
    __syncthreads();

    int c = t;
    u64 acc2[PN/2];
    #pragma unroll
    for (int p = 0; p < PN/2; p++) acc2[p] = 0ull;

    #pragma unroll
    for (int ck = 0; ck < 8; ck++) {
        int buf = ck & 1;
        #pragma unroll
        for (int kk = 0; kk < 16; kk++) {
            float w = sw[buf][kk][c];
            u64 w2 = pk2(w, w);
            const ulonglong2* hp = (const ulonglong2*)&sph[ck*16 + kk][0];
            ulonglong2 h01 = hp[0], h23 = hp[1];
            acc2[0] = fmax2(h01.x, w2, acc2[0]);
            acc2[1] = fmax2(h01.y, w2, acc2[1]);
            acc2[2] = fmax2(h23.x, w2, acc2[2]);
            acc2[3] = fmax2(h23.y, w2, acc2[3]);
        }
        if (ck < 7) {
            sts_chunk((ck + 1) & 1);
            if (ck < 6) ldg_chunk(ck + 2);
            __syncthreads();
        }
    }

    int sel = c >> 7, d = c & 127;
    float* g = sel ? d_gr : d_gl;
    #pragma unroll
    for (int p = 0; p < PN/2; p++) {
        float2 v = unpk2(acc2[p]);
        g[(n0 + 2*p)*DH + d]     = v.x;
        g[(n0 + 2*p + 1)*DH + d] = v.y;
    }
    if (sel == 0) {
        float av = 0.6f * LOG2E * a[d & 15];    // pre-scaled by log2e for ex2
        u64 av2 = pk2(av, av);
        u64 pr[PN/2];
        #pragma unroll
        for (int p = 0; p < PN/2; p++) pr[p] = mulx2(acc2[p], av2);
        #pragma unroll
        for (int off = 8; off; off >>= 1) {
            #pragma unroll
            for (int p = 0; p < PN/2; p++)
                pr[p] = addx2(pr[p], __shfl_down_sync(0xffffffffu, pr[p], off, 16));
        }
        if ((d & 15) == 0) {
            int hh = d >> 4;
            #pragma unroll
            for (int p = 0; p < PN/2; p++) {
                float2 v = unpk2(pr[p]);
                d_dl[(n0 + 2*p)*HH + hh]     = v.x;
                d_dl[(n0 + 2*p + 1)*HH + hh] = v.y;
            }
        }
    }
}

// ---- fused GATv2 attention: 64-i tile per block, 2 i per thread ----
// e2_j = log2e*[0.6(a.gl_j) + sum_f 0.4 a_f |gr_i + gl_j|_f]; p = 2^e2 (no-max
// softmax: logits O(30), fp32-safe; per-i shift dropped by shift-invariance).
// 16 warps, warp owns 32 j; its j-tile is read once from smem and consumed by
// BOTH i-streams (i, i+32) -> per-(i,j) LDS cost halved vs one-i version.
__global__ void __launch_bounds__(512) attn_kernel(const float* __restrict__ a,
                                                   const float* __restrict__ Wout,
                                                   float* __restrict__ out,
                                                   int src, int last)
{
    // pool: compute phase = per-warp j-tiles (gl at j*16+0..7, gr at +8..15);
    // merge phase (after __syncthreads) = acc staging at (w*32+lane)*9 + q.
    __shared__ __align__(16) u64 s_pool[AW*288];           // 36KB
    __shared__ float s_dl[AW][TJ];
    __shared__ float s_l[AW][32];

    int blk   = blockIdx.x;
    int itile = blk & 7;                      // N/64 = 8
    int hh    = (blk >> 3) & 7;
    int b     = blk >> 6;
    int wq    = threadIdx.x >> 5;             // 0..15, owns j in [wq*32, wq*32+32)
    int lane  = threadIdx.x & 31;
    int i0    = itile * 64 + lane;
    int ni0   = b * NN + i0;
    int ni1   = ni0 + 32;

    u64 ar2[FF/2];
    #pragma unroll
    for (int q = 0; q < FF/2; q++)
        ar2[q] = pk2(0.4f * LOG2E * a[2*q], 0.4f * LOG2E * a[2*q+1]);

    u64 gri2a[FF/2], gri2b[FF/2];
    {
        const ulonglong2* gpa = (const ulonglong2*)(d_gr + (ni0*HH + hh)*FF);
        const ulonglong2* gpb = (const ulonglong2*)(d_gr + (ni1*HH + hh)*FF);
        #pragma unroll
        for (int q = 0; q < 4; q++) {
            ulonglong2 va = gpa[q], vb = gpb[q];
            gri2a[2*q] = va.x; gri2a[2*q+1] = va.y;
            gri2b[2*q] = vb.x; gri2b[2*q+1] = vb.y;
        }
    }

    const float*    glbase = d_gl + (b*NN*HH + hh)*FF;
    const float*    grbase = d_gr + (b*NN*HH + hh)*FF;
    const unsigned* abr0   = d_adjbits + ni0*(NN/32);
    const unsigned* abr1   = d_adjbits + ni1*(NN/32);

    float la = 0.f, lb = 0.f;
    u64 acc2a[FF/2], acc2b[FF/2];
    #pragma unroll
    for (int q = 0; q < FF/2; q++) { acc2a[q] = 0ull; acc2b[q] = 0ull; }

    u64* tile = &s_pool[wq * 288];

    #pragma unroll
    for (int t = 0; t < 2; t++) {                // 2 tiles of 16 j per warp
        int j0 = wq * 32 + t * TJ;
        __syncwarp();
        #pragma unroll
        for (int r = 0; r < 2; r++) {
            int idx = lane + r*32;               // 0..63 float4s per array
            int j = idx >> 2, v = idx & 3;
            *(float4*)&tile[j*16 + v*2]     = *((const float4*)(glbase + (j0+j)*(HH*FF)) + v);
            *(float4*)&tile[j*16 + 8 + v*2] = *((const float4*)(grbase + (j0+j)*(HH*FF)) + v);
        }
        if (lane < TJ) s_dl[wq][lane] = d_dl[(b*NN + j0 + lane)*HH + hh];
        __syncwarp();

        unsigned mba = abr0[j0 >> 5] >> (j0 & 31);
        unsigned mbb = abr1[j0 >> 5] >> (j0 & 31);
        #pragma unroll
        for (int j = 0; j < TJ; j++) {
            const ulonglong2* g2 = (const ulonglong2*)&tile[j*16];
            u64 s0a = 0ull, s1a = 0ull, s0b = 0ull, s1b = 0ull;
            #pragma unroll
            for (int q = 0; q < 4; q++) {
                ulonglong2 gv = g2[q];
                u64 t0a = addx2(gri2a[2*q],   gv.x) & ABSMASK2;
                u64 t1a = addx2(gri2a[2*q+1], gv.y) & ABSMASK2;
                s0a = fmax2(ar2[2*q],   t0a, s0a);
                s1a = fmax2(ar2[2*q+1], t1a, s1a);
                u64 t0b = addx2(gri2b[2*q],   gv.x) & ABSMASK2;
                u64 t1b = addx2(gri2b[2*q+1], gv.y) & ABSMASK2;
                s0b = fmax2(ar2[2*q],   t0b, s0b);
                s1b = fmax2(ar2[2*q+1], t1b, s1b);
            }
            float2 sva = unpk2(addx2(s0a, s1a));
            float2 svb = unpk2(addx2(s0b, s1b));
            float dl = s_dl[wq][j];
            float pa = ((mba >> j) & 1u) ? ex2((sva.x + sva.y) + dl) : 0.f;
            float pb = ((mbb >> j) & 1u) ? ex2((svb.x + svb.y) + dl) : 0.f;
            la += pa; lb += pb;
            u64 p2a = pk2(pa, pa), p2b = pk2(pb, pb);
            const ulonglong2* gr2 = (const ulonglong2*)&tile[j*16 + 8];
            #pragma unroll
            for (int q = 0; q < 4; q++) {
                ulonglong2 gv = gr2[q];
                acc2a[2*q]   = fmax2(p2a, gv.x, acc2a[2*q]);
                acc2a[2*q+1] = fmax2(p2a, gv.y, acc2a[2*q+1]);
                acc2b[2*q]   = fmax2(p2b, gv.x, acc2b[2*q]);
                acc2b[2*q+1] = fmax2(p2b, gv.y, acc2b[2*q+1]);
            }
        }
    }

    // ---- two-pass parallel merge (pool reused; warp q<8 owns component q) ----
    __syncthreads();                             // tiles consumed
    s_l[wq][lane] = la;
    #pragma unroll
    for (int q = 0; q < FF/2; q++)
        s_pool[(wq*32 + lane)*9 + q] = acc2a[q];
    __syncthreads();

    if (wq < 8) {
        int q = wq;
        float L = 0.f;
        u64 o = 0ull;
        #pragma unroll
        for (int w = 0; w < AW; w++) {
            L += s_l[w][lane];
            o = addx2(o, s_pool[(w*32 + lane)*9 + q]);
        }
        float inv = 1.f / L;
        if (!last) {
            u64* ho = (u64*)(d_h[src ^ 1] + (ni0*HH + hh)*FF);
            ho[q] = mulx2(o, pk2(inv, inv));
        } else {
            const float* wo = Wout + hh*FF;
            float2 ov = unpk2(o);
            atomicAdd(&out[ni0], (ov.x * wo[2*q] + ov.y * wo[2*q+1]) * inv);
        }
    }
    __syncthreads();                             // merge-A reads done

    s_l[wq][lane] = lb;
    #pragma unroll
    for (int q = 0; q < FF/2; q++)
        s_pool[(wq*32 + lane)*9 + q] = acc2b[q];
    __syncthreads();

    if (wq < 8) {
        int q = wq;
        float L = 0.f;
        u64 o = 0ull;
        #pragma unroll
        for (int w = 0; w < AW; w++) {
            L += s_l[w][lane];
            o = addx2(o, s_pool[(w*32 + lane)*9 + q]);
        }
        float inv = 1.f / L;
        if (!last) {
            u64* ho = (u64*)(d_h[src ^ 1] + (ni1*HH + hh)*FF);
            ho[q] = mulx2(o, pk2(inv, inv));
        } else {
            const float* wo = Wout + hh*FF;
            float2 ov = unpk2(o);
            atomicAdd(&out[ni1], (ov.x * wo[2*q] + ov.y * wo[2*q+1]) * inv);
        }
    }
}

extern "C" void kernel_launch(void* const* d_in, const int* in_sizes, int n_in,
                              void* d_out, int out_size)
{
    const float* nf   = (const float*)d_in[0];
    const int*   adj  = (const int*)  d_in[1];
    const float* Win  = (const float*)d_in[2];
    const float* Wl   = (const float*)d_in[3];
    const float* Wr   = (const float*)d_in[4];
    const float* aa   = (const float*)d_in[5];
    const float* Wout = (const float*)d_in[6];
    float* out = (float*)d_out;
    (void)in_sizes; (void)n_in; (void)out_size;

    zero_kernel<<<8, 256>>>(out);
    prep_kernel<<<1024 + 256, 256>>>(nf, Win, adj);
    for (int L = 0; L < 3; L++) {
        int src = L & 1;
        proj_kernel<<<(BB*NN)/PN, 256>>>(Wl + L*DH*DH, Wr + L*DH*DH, aa + L*FF, src);
        attn_kernel<<<BB*HH*(NN/64), 512>>>(aa + L*FF, Wout, out, src, L == 2);
    }
}